// round 8
// baseline (speedup 1.0000x reference)
#include <cuda_runtime.h>
#include <cstdint>
#include <cstddef>

// Persistent fused 2-layer LSTM (B=64, T=1500, F=36, H=512) + projection.
// 128 blocks x 256 threads, one grid barrier per pipelined interval.

#define NBLK 128
#define NTH  256
#define B_   64
#define T_   1500
#define F_   36
#define H_   512
#define C_   64
#define K2H  256   // H/2
#define K2F  18    // F/2

typedef unsigned long long ull;

// Hidden-state ping-pong: [parity][k2][batch], float2 = (h[2k2], h[2k2+1]).
__device__ __align__(16) float2 g_hA[2][K2H][B_];
__device__ __align__(16) float2 g_hB[2][K2H][B_];

// Monotonic grid-barrier counters (persist across graph replays).
__device__ unsigned g_arrive  = 0;
__device__ unsigned g_release = 0;

struct __align__(16) Smem {
    float2 wA[K2H][4][4];     // layer0 W_hh  [k2][unit][gate]
    float2 wI[K2H][4][4];     // layer1 W_ih
    float2 wH[K2H][4][4];     // layer1 W_hh
    float2 wX[K2F][4][4];     // layer0 W_ih
    float2 xbuf[2][K2F][B_];  // staged x[t] ping-pong
    float  red0[4][16][65];   // cross-warp partials (padded)
    float  red1[4][16][65];
    float  gatesA[16][66];
    float  gatesB[16][66];
    float  cA[4][B_];
    float  cB[4][B_];
    float  biasA[16];
    float  biasB[16];
};

__device__ __forceinline__ void ffma2(ull &d, ull a, ull b) {
    asm("fma.rn.f32x2 %0, %1, %2, %0;" : "+l"(d) : "l"(a), "l"(b));
}
__device__ __forceinline__ ull  d2u(double d)  { return (ull)__double_as_longlong(d); }
__device__ __forceinline__ float lo32(ull v)   { return __uint_as_float((unsigned)(v & 0xffffffffull)); }
__device__ __forceinline__ float hi32(ull v)   { return __uint_as_float((unsigned)(v >> 32)); }
__device__ __forceinline__ float sigf(float x) { return 1.0f / (1.0f + expf(-x)); }

__device__ __forceinline__ void grid_bar(unsigned target, int tid) {
    __threadfence();
    __syncthreads();
    if (tid == 0) {
        unsigned arrived = atomicAdd(&g_arrive, 1u) + 1u;
        if (arrived == target * (unsigned)NBLK) {
            atomicExch(&g_release, target);
        } else {
            while ((int)(*(volatile unsigned *)&g_release - target) < 0) { }
        }
        __threadfence();
    }
    __syncthreads();
}

extern "C" __global__ void __launch_bounds__(NTH, 1)
lstm2_persistent_kernel(const float* __restrict__ x,
                        const float* __restrict__ W_ih0, const float* __restrict__ W_hh0,
                        const float* __restrict__ b_ih0, const float* __restrict__ b_hh0,
                        const float* __restrict__ W_ih1, const float* __restrict__ W_hh1,
                        const float* __restrict__ b_ih1, const float* __restrict__ b_hh1,
                        const float* __restrict__ W_out, const float* __restrict__ b_out,
                        float* __restrict__ out)
{
    extern __shared__ char smraw[];
    Smem& s = *reinterpret_cast<Smem*>(smraw);
    const int tid  = threadIdx.x;
    const int blk  = blockIdx.x;
    const int wid  = tid >> 5;
    const int lane = tid & 31;
    const int bh   = wid & 1;           // batch half
    const int kc   = wid >> 1;          // k-chunk (0..3), 64 k2 each
    const int u    = lane >> 3;         // hidden unit in block (0..3)
    const int bg   = lane & 7;          // batch group
    const int bb   = bh * 32 + bg * 4;  // batch base

    __shared__ unsigned s_base;
    if (tid == 0) s_base = *(volatile unsigned *)&g_release;

    // ---- startup: weights + biases -> SMEM, zero state ---------------------
    const int row_base = blk * 4;
    for (int idx = tid; idx < K2H * 16; idx += NTH) {
        int k2 = idx >> 4, r = idx & 15, uu = r >> 2, gt = r & 3;
        int row = gt * H_ + row_base + uu;
        s.wA[k2][uu][gt] = make_float2(W_hh0[row * H_ + 2 * k2], W_hh0[row * H_ + 2 * k2 + 1]);
        s.wI[k2][uu][gt] = make_float2(W_ih1[row * H_ + 2 * k2], W_ih1[row * H_ + 2 * k2 + 1]);
        s.wH[k2][uu][gt] = make_float2(W_hh1[row * H_ + 2 * k2], W_hh1[row * H_ + 2 * k2 + 1]);
    }
    for (int idx = tid; idx < K2F * 16; idx += NTH) {
        int k2 = idx >> 4, r = idx & 15, uu = r >> 2, gt = r & 3;
        int row = gt * H_ + row_base + uu;
        s.wX[k2][uu][gt] = make_float2(W_ih0[row * F_ + 2 * k2], W_ih0[row * F_ + 2 * k2 + 1]);
    }
    if (tid < 16) {
        int uu = tid >> 2, gt = tid & 3;
        int row = gt * H_ + row_base + uu;
        s.biasA[uu * 4 + gt] = b_ih0[row] + b_hh0[row];
        s.biasB[uu * 4 + gt] = b_ih1[row] + b_hh1[row];
    }
    for (int idx = tid; idx < 4 * B_; idx += NTH) {
        s.cA[idx >> 6][idx & 63] = 0.0f;
        s.cB[idx >> 6][idx & 63] = 0.0f;
    }
    for (int idx = tid; idx < 2 * 2 * B_; idx += NTH) {
        int p = idx >> 7, q = (idx >> 6) & 1, b = idx & 63;
        g_hA[p][blk * 2 + q][b] = make_float2(0.0f, 0.0f);
        g_hB[p][blk * 2 + q][b] = make_float2(0.0f, 0.0f);
    }
    for (int idx = tid; idx < K2F * B_; idx += NTH) {
        int b = idx & 63, f2 = idx >> 6;
        const float* xp = x + ((size_t)b * T_) * F_ + 2 * f2;
        s.xbuf[0][f2][b] = make_float2(__ldg(xp), __ldg(xp + 1));
    }
    __syncthreads();
    const unsigned base = s_base;
    grid_bar(base + 1, tid);

    const int k2b = kc * 64;

    // ---- main loop: T_+1 pipelined intervals -------------------------------
    for (int n = 0; n <= T_; ++n) {
        const int par = n & 1;
        const float2* aprev = &g_hA[par][0][0];
        const float2* bprev = &g_hB[par][0][0];
        float2* awr = &g_hA[par ^ 1][0][0];
        float2* bwr = &g_hB[par ^ 1][0][0];

        // phase 1: accA = W_hh0 . h1_prev ; accI = W_ih1 . h1_prev
        ull accA[16], accI[16];
        #pragma unroll
        for (int j = 0; j < 16; ++j) { accA[j] = 0ull; accI[j] = 0ull; }
        {
            const double2* hp = reinterpret_cast<const double2*>(aprev + (size_t)k2b * B_ + bb);
            #pragma unroll 4
            for (int k2 = k2b; k2 < k2b + 64; ++k2) {
                double2 h01 = __ldcg(hp);
                double2 h23 = __ldcg(hp + 1);
                hp += 32;
                double2 wa01 = *reinterpret_cast<const double2*>(&s.wA[k2][u][0]);
                double2 wa23 = *reinterpret_cast<const double2*>(&s.wA[k2][u][2]);
                double2 wi01 = *reinterpret_cast<const double2*>(&s.wI[k2][u][0]);
                double2 wi23 = *reinterpret_cast<const double2*>(&s.wI[k2][u][2]);
                ull hb[4] = { d2u(h01.x), d2u(h01.y), d2u(h23.x), d2u(h23.y) };
                ull wa[4] = { d2u(wa01.x), d2u(wa01.y), d2u(wa23.x), d2u(wa23.y) };
                ull wi[4] = { d2u(wi01.x), d2u(wi01.y), d2u(wi23.x), d2u(wi23.y) };
                #pragma unroll
                for (int gt = 0; gt < 4; ++gt)
                    #pragma unroll
                    for (int bj = 0; bj < 4; ++bj) {
                        ffma2(accA[gt * 4 + bj], hb[bj], wa[gt]);
                        ffma2(accI[gt * 4 + bj], hb[bj], wi[gt]);
                    }
            }
        }
        // layer0 input term: accA += W_ih0 . x[n]
        if (n < T_) {
            const int xp = n & 1;
            const int xs = (K2F * kc) / 4, xe = (K2F * (kc + 1)) / 4;
            for (int k2 = xs; k2 < xe; ++k2) {
                double2 h01 = *reinterpret_cast<const double2*>(&s.xbuf[xp][k2][bb]);
                double2 h23 = *reinterpret_cast<const double2*>(&s.xbuf[xp][k2][bb + 2]);
                double2 wx01 = *reinterpret_cast<const double2*>(&s.wX[k2][u][0]);
                double2 wx23 = *reinterpret_cast<const double2*>(&s.wX[k2][u][2]);
                ull hb[4] = { d2u(h01.x), d2u(h01.y), d2u(h23.x), d2u(h23.y) };
                ull wx[4] = { d2u(wx01.x), d2u(wx01.y), d2u(wx23.x), d2u(wx23.y) };
                #pragma unroll
                for (int gt = 0; gt < 4; ++gt)
                    #pragma unroll
                    for (int bj = 0; bj < 4; ++bj)
                        ffma2(accA[gt * 4 + bj], hb[bj], wx[gt]);
            }
        }
        #pragma unroll
        for (int gt = 0; gt < 4; ++gt)
            #pragma unroll
            for (int bj = 0; bj < 4; ++bj) {
                s.red0[kc][u * 4 + gt][bb + bj] = lo32(accA[gt * 4 + bj]) + hi32(accA[gt * 4 + bj]);
                s.red1[kc][u * 4 + gt][bb + bj] = lo32(accI[gt * 4 + bj]) + hi32(accI[gt * 4 + bj]);
            }
        __syncthreads();
        {
            int r = tid >> 4, b0 = (tid & 15) * 4;
            #pragma unroll
            for (int j = 0; j < 4; ++j) {
                int b = b0 + j;
                s.gatesA[r][b] = s.red0[0][r][b] + s.red0[1][r][b] + s.red0[2][r][b] + s.red0[3][r][b] + s.biasA[r];
                s.gatesB[r][b] = s.red1[0][r][b] + s.red1[1][r][b] + s.red1[2][r][b] + s.red1[3][r][b] + s.biasB[r];
            }
        }
        __syncthreads();

        // phase 2: accH = W_hh1 . h2_prev
        ull accH[16];
        #pragma unroll
        for (int j = 0; j < 16; ++j) accH[j] = 0ull;
        {
            const double2* hp = reinterpret_cast<const double2*>(bprev + (size_t)k2b * B_ + bb);
            #pragma unroll 4
            for (int k2 = k2b; k2 < k2b + 64; ++k2) {
                double2 h01 = __ldcg(hp);
                double2 h23 = __ldcg(hp + 1);
                hp += 32;
                double2 wh01 = *reinterpret_cast<const double2*>(&s.wH[k2][u][0]);
                double2 wh23 = *reinterpret_cast<const double2*>(&s.wH[k2][u][2]);
                ull hb[4] = { d2u(h01.x), d2u(h01.y), d2u(h23.x), d2u(h23.y) };
                ull wh[4] = { d2u(wh01.x), d2u(wh01.y), d2u(wh23.x), d2u(wh23.y) };
                #pragma unroll
                for (int gt = 0; gt < 4; ++gt)
                    #pragma unroll
                    for (int bj = 0; bj < 4; ++bj)
                        ffma2(accH[gt * 4 + bj], hb[bj], wh[gt]);
            }
        }
        #pragma unroll
        for (int gt = 0; gt < 4; ++gt)
            #pragma unroll
            for (int bj = 0; bj < 4; ++bj)
                s.red0[kc][u * 4 + gt][bb + bj] = lo32(accH[gt * 4 + bj]) + hi32(accH[gt * 4 + bj]);
        __syncthreads();
        {
            int r = tid >> 4, b0 = (tid & 15) * 4;
            #pragma unroll
            for (int j = 0; j < 4; ++j) {
                int b = b0 + j;
                s.gatesB[r][b] += s.red0[0][r][b] + s.red0[1][r][b] + s.red0[2][r][b] + s.red0[3][r][b];
            }
        }
        __syncthreads();

        // elementwise cell updates + h writes
        {
            int uu = tid >> 6, b = tid & 63;
            if (n < T_) {  // layer0 step n
                float gi = sigf(s.gatesA[uu * 4 + 0][b]);
                float gf = sigf(s.gatesA[uu * 4 + 1][b]);
                float gg = tanhf(s.gatesA[uu * 4 + 2][b]);
                float go = sigf(s.gatesA[uu * 4 + 3][b]);
                float c  = gf * s.cA[uu][b] + gi * gg;
                s.cA[uu][b] = c;
                reinterpret_cast<float*>(&awr[(blk * 2 + (uu >> 1)) * B_ + b])[uu & 1] = go * tanhf(c);
            }
            if (n >= 1) {  // layer1 step n-1
                float gi = sigf(s.gatesB[uu * 4 + 0][b]);
                float gf = sigf(s.gatesB[uu * 4 + 1][b]);
                float gg = tanhf(s.gatesB[uu * 4 + 2][b]);
                float go = sigf(s.gatesB[uu * 4 + 3][b]);
                float c  = gf * s.cB[uu][b] + gi * gg;
                s.cB[uu][b] = c;
                reinterpret_cast<float*>(&bwr[(blk * 2 + (uu >> 1)) * B_ + b])[uu & 1] = go * tanhf(c);
            }
        }
        // stage x for interval n+1 (hides in the barrier spin)
        if (n + 1 < T_) {
            const int xp = (n + 1) & 1;
            for (int idx = tid; idx < K2F * B_; idx += NTH) {
                int b = idx & 63, f2 = idx >> 6;
                const float* xpp = x + ((size_t)b * T_ + (n + 1)) * F_ + 2 * f2;
                s.xbuf[xp][f2][b] = make_float2(__ldg(xpp), __ldg(xpp + 1));
            }
        }
        grid_bar(base + 2 + (unsigned)n, tid);
    }

    // ---- projection: out[b][c] = h2_last[b] . W_out[c] + b_out[c] ----------
    // h2 final (step T_-1) was written in interval n=T_ (par=0) into g_hB[1].
    if (blk < C_) {
        const int c = blk;
        const int b = tid & 63, q = tid >> 6;   // q: quarter of H
        float acc = 0.0f;
        const float2* wp = reinterpret_cast<const float2*>(W_out + (size_t)c * H_) + q * 64;
        #pragma unroll 8
        for (int k2 = 0; k2 < 64; ++k2) {
            float2 hv = g_hB[1][q * 64 + k2][b];
            float2 wv = __ldg(wp + k2);
            acc += hv.x * wv.x + hv.y * wv.y;
        }
        float* sred = &s.red0[0][0][0];
        sred[q * 64 + b] = acc;
        __syncthreads();
        if (q == 0)
            out[(size_t)b * C_ + c] = sred[b] + sred[64 + b] + sred[128 + b] + sred[192 + b] + b_out[c];
    }
}

extern "C" void kernel_launch(void* const* d_in, const int* in_sizes, int n_in,
                              void* d_out, int out_size) {
    (void)in_sizes; (void)n_in; (void)out_size;
    const float* x     = (const float*)d_in[0];
    const float* W_ih0 = (const float*)d_in[1];
    const float* W_hh0 = (const float*)d_in[2];
    const float* b_ih0 = (const float*)d_in[3];
    const float* b_hh0 = (const float*)d_in[4];
    const float* W_ih1 = (const float*)d_in[5];
    const float* W_hh1 = (const float*)d_in[6];
    const float* b_ih1 = (const float*)d_in[7];
    const float* b_hh1 = (const float*)d_in[8];
    const float* W_out = (const float*)d_in[9];
    const float* b_out = (const float*)d_in[10];
    float* out = (float*)d_out;

    size_t smem = sizeof(Smem);
    cudaFuncSetAttribute(lstm2_persistent_kernel,
                         cudaFuncAttributeMaxDynamicSharedMemorySize, (int)smem);
    lstm2_persistent_kernel<<<NBLK, NTH, smem>>>(
        x, W_ih0, W_hh0, b_ih0, b_hh0, W_ih1, W_hh1, b_ih1, b_hh1, W_out, b_out, out);
}